// round 16
// baseline (speedup 1.0000x reference)
#include <cuda_runtime.h>
#include <cuda_bf16.h>

#define RES   1024
#define FEAT  12
#define NCB   32
#define HIMG  1080
#define WIMG  1920
#define NPIX  (HIMG*WIMG)       // 2,073,600 = 4050 * 512
#define NT    256
#define PIX_PER_BLOCK 512

struct Consts {
    float W1d[3*32];    // W1 rows 12..14 (direction weights), [r][j]
    float L1P[32*32];   // B1 + W1[0:12]^T cb[c], [c][j]
    float W2[32*32];    // [k][j]
    float B2[32];
    float W3[32*3];     // [k][c]
    float B3[3];
    float pad;
    float CB[NCB*FEAT];
    float C2[NCB];
};
__device__ Consts g_stage;
__constant__ Consts cC;

__global__ void setup_kernel(const float* __restrict__ W1, const float* __restrict__ b1,
                             const float* __restrict__ W2, const float* __restrict__ b2,
                             const float* __restrict__ W3, const float* __restrict__ b3,
                             const float* __restrict__ cbk)
{
    const int t = threadIdx.x;     // 1024 threads
    if (t == 0) g_stage.pad = 0.f;
    if (t < 96)  g_stage.W1d[t] = W1[12*32 + t];          // rows 12..14
    {
        const int c = t >> 5, j = t & 31;
        float a = b1[j];
        #pragma unroll
        for (int k = 0; k < FEAT; k++) a += cbk[c*FEAT + k] * W1[k*32 + j];
        g_stage.L1P[t] = a;
    }
    g_stage.W2[t] = W2[t];         // exactly 1024
    if (t < 32)  g_stage.B2[t] = b2[t];
    if (t < 96)  g_stage.W3[t] = W3[t];
    if (t < 3)   g_stage.B3[t] = b3[t];
    if (t < NCB*FEAT) g_stage.CB[t] = cbk[t];
    if (t < NCB) {
        float a = 0.f;
        #pragma unroll
        for (int k = 0; k < FEAT; k++) { float v = cbk[t*FEAT + k]; a += v*v; }
        g_stage.C2[t] = a;
    }
}

__device__ __forceinline__ void load12(const float* __restrict__ p, float* dst) {
    float4 a = *(const float4*)(p);
    float4 b = *(const float4*)(p + 4);
    float4 c = *(const float4*)(p + 8);
    dst[0]=a.x; dst[1]=a.y; dst[2]=a.z;  dst[3]=a.w;
    dst[4]=b.x; dst[5]=b.y; dst[6]=b.z;  dst[7]=b.w;
    dst[8]=c.x; dst[9]=c.y; dst[10]=c.z; dst[11]=c.w;
}

__global__ __launch_bounds__(NT, 4)
void sky_kernel(const float* __restrict__ rays,
                const int* __restrict__ mask,
                const float* __restrict__ cube,
                float* __restrict__ out)
{
    __shared__ float sL1P[32*33];            // stride-33: divergent row gather, conflict-free
    __shared__ float sW2[32*32];             // layer-2 weights: broadcast LDS, off the LDC port
    __shared__ float sRay[PIX_PER_BLOCK*3];  // block's rays, staged coalesced
    __shared__ int   sIdx[PIX_PER_BLOCK];
    __shared__ int   sCnt;

    const int tid  = threadIdx.x;
    const int lane = tid & 31;
    for (int j = tid; j < 32*32; j += NT) {
        sL1P[(j >> 5)*33 + (j & 31)] = cC.L1P[j];
        sW2[j] = cC.W2[j];
    }
    if (tid == 0) sCnt = 0;

    // stage rays for this block's 512-pixel window (coalesced float4 loads)
    const int base = blockIdx.x * PIX_PER_BLOCK;
    {
        const float4* __restrict__ rsrc = (const float4*)(rays + (size_t)3 * base);
        float4* __restrict__ rdst = (float4*)sRay;
        #pragma unroll
        for (int j = 0; j < (PIX_PER_BLOCK*3/4 + NT - 1) / NT; j++) {
            const int idx = j * NT + tid;
            if (idx < PIX_PER_BLOCK*3/4) rdst[idx] = rsrc[idx];
        }
    }
    __syncthreads();

    // ---- phase 1: block-local compaction over 512 pixels + zero fills ----
    #pragma unroll
    for (int r = 0; r < PIX_PER_BLOCK / NT; r++) {
        const int pix = base + r * NT + tid;
        const bool active = (mask[pix] != 0);
        if (!active) {
            out[pix]          = 0.f;
            out[NPIX + pix]   = 0.f;
            out[2*NPIX + pix] = 0.f;
        }
        const unsigned bal = __ballot_sync(0xFFFFFFFFu, active);
        int wbase = 0;
        if (lane == 0) wbase = atomicAdd(&sCnt, __popc(bal));
        wbase = __shfl_sync(0xFFFFFFFFu, wbase, 0);
        if (active) sIdx[wbase + __popc(bal & ((1u << lane) - 1u))] = r * NT + tid;
    }
    __syncthreads();
    const int cnt = sCnt;

    // ---- phase 2: process compacted pixels with full warps ----
    for (int i = tid; i < cnt; i += NT) {
        const int li  = sIdx[i];
        const int pix = base + li;

        const float x = sRay[3*li+0], y = sRay[3*li+1], z = sRay[3*li+2];
        const float ax = fabsf(x), ay = fabsf(y), az = fabsf(z);
        const bool is_x = (ax >= ay) && (ax >= az);
        const bool is_y = (!is_x) && (ay >= az);

        int face; float ma, u, v;
        if (is_x)      { face = (x >= 0.f) ? 0 : 1; ma = ax; u = (x >= 0.f) ? -z : z; v = -y; }
        else if (is_y) { face = (y >= 0.f) ? 2 : 3; ma = ay; u = x; v = (y >= 0.f) ? z : -z; }
        else           { face = (z >= 0.f) ? 4 : 5; ma = az; u = (z >= 0.f) ? x : -x; v = -y; }

        const float inv = __fdividef(1.f, ma + 1e-9f);
        const float sc = (u*inv + 1.f) * 0.5f * (float)RES - 0.5f;
        const float tc = (v*inv + 1.f) * 0.5f * (float)RES - 0.5f;
        const float fs = floorf(sc), ft = floorf(tc);
        const float fx = sc - fs, fy = tc - ft;
        int x0 = (int)fs; x0 = max(0, min(x0, RES-1));
        const int x1 = min(x0+1, RES-1);
        int y0 = (int)ft; y0 = max(0, min(y0, RES-1));
        const int y1 = min(y0+1, RES-1);

        const float* __restrict__ fb = cube + (size_t)face * (size_t)(RES*RES*FEAT);

        float feat[FEAT], tmp[FEAT], bot[FEAT];
        load12(fb + ((size_t)y0*RES + x0)*FEAT, feat);
        load12(fb + ((size_t)y0*RES + x1)*FEAT, tmp);
        #pragma unroll
        for (int k = 0; k < FEAT; k++) feat[k] = feat[k]*(1.f-fx) + tmp[k]*fx;
        load12(fb + ((size_t)y1*RES + x0)*FEAT, bot);
        load12(fb + ((size_t)y1*RES + x1)*FEAT, tmp);
        #pragma unroll
        for (int k = 0; k < FEAT; k++) bot[k] = bot[k]*(1.f-fx) + tmp[k]*fx;
        #pragma unroll
        for (int k = 0; k < FEAT; k++) feat[k] = feat[k]*(1.f-fy) + bot[k]*fy;

        // nearest codebook: argmin_c (C2[c] - 2*dot), first-min-wins
        int best = 0;
        float bestd = 3.4e38f;
        #pragma unroll
        for (int c = 0; c < NCB; c++) {
            float dot = 0.f;
            #pragma unroll
            for (int k = 0; k < FEAT; k++) dot += feat[k]*cC.CB[c*FEAT + k];
            const float d2 = cC.C2[c] - 2.f*dot;
            if (d2 < bestd) { bestd = d2; best = c; }
        }

        // layer 1 (collapsed): relu(L1P[best] + x*W1[12] + y*W1[13] + z*W1[14])
        const float* __restrict__ rowp = sL1P + best*33;
        float h[32];
        #pragma unroll
        for (int j = 0; j < 32; j++) {
            float a = rowp[j];
            a += x * cC.W1d[j];
            a += y * cC.W1d[32 + j];
            a += z * cC.W1d[64 + j];
            h[j] = fmaxf(a, 0.f);
        }

        // layer 2: 32 -> 32, relu — weights via broadcast LDS (off the constant port)
        float h2[32];
        #pragma unroll
        for (int j = 0; j < 32; j++) h2[j] = cC.B2[j];
        #pragma unroll
        for (int k = 0; k < 32; k++) {
            const float iv = h[k];
            #pragma unroll
            for (int j = 0; j < 32; j++) h2[j] += iv * sW2[k*32 + j];
        }
        #pragma unroll
        for (int j = 0; j < 32; j++) h2[j] = fmaxf(h2[j], 0.f);

        // layer 3: 32 -> 3, sigmoid
        float r0 = cC.B3[0], r1 = cC.B3[1], r2 = cC.B3[2];
        #pragma unroll
        for (int k = 0; k < 32; k++) {
            const float iv = h2[k];
            r0 += iv * cC.W3[k*3 + 0];
            r1 += iv * cC.W3[k*3 + 1];
            r2 += iv * cC.W3[k*3 + 2];
        }
        // sigmoid is already in (0,1): ref's clip is a no-op for active pixels
        out[pix]          = __fdividef(1.f, 1.f + __expf(-r0));
        out[NPIX + pix]   = __fdividef(1.f, 1.f + __expf(-r1));
        out[2*NPIX + pix] = __fdividef(1.f, 1.f + __expf(-r2));
    }
}

extern "C" void kernel_launch(void* const* d_in, const int* in_sizes, int n_in,
                              void* d_out, int out_size)
{
    const float* rays = (const float*)d_in[0];
    const int*   mask = (const int*)d_in[1];
    const float* cube = (const float*)d_in[2];
    const float* cbk  = (const float*)d_in[3];
    const float* W1   = (const float*)d_in[4];
    const float* b1   = (const float*)d_in[5];
    const float* W2   = (const float*)d_in[6];
    const float* b2   = (const float*)d_in[7];
    const float* W3   = (const float*)d_in[8];
    const float* b3   = (const float*)d_in[9];
    float* out = (float*)d_out;

    setup_kernel<<<1, 1024>>>(W1, b1, W2, b2, W3, b3, cbk);

    void* stage_ptr = nullptr;
    cudaGetSymbolAddress(&stage_ptr, g_stage);
    cudaMemcpyToSymbolAsync(cC, stage_ptr, sizeof(Consts), 0, cudaMemcpyDeviceToDevice, 0);

    sky_kernel<<<NPIX / PIX_PER_BLOCK, NT>>>(rays, mask, cube, out);
}

// round 17
// speedup vs baseline: 2.5248x; 2.5248x over previous
#include <cuda_runtime.h>
#include <cuda_bf16.h>

#define RES   1024
#define FEAT  12
#define NCB   32
#define HIMG  1080
#define WIMG  1920
#define NPIX  (HIMG*WIMG)       // 2,073,600 = 4050 * 512
#define NT    256
#define PIX_PER_BLOCK 512

struct Consts {
    float W1d[3*32];    // W1 rows 12..14 (direction weights), [r][j]
    float L1P[32*32];   // B1 + W1[0:12]^T cb[c], [c][j]
    float W2[32*32];    // [k][j]
    float B2[32];
    float W3T[3*32];    // TRANSPOSED [c][k]: consecutive-k reads vectorize to LDC.128
    float B3[3];
    float pad;
    float CB[NCB*FEAT];
    float C2[NCB];
};
__device__ Consts g_stage;
__constant__ Consts cC;

__global__ void setup_kernel(const float* __restrict__ W1, const float* __restrict__ b1,
                             const float* __restrict__ W2, const float* __restrict__ b2,
                             const float* __restrict__ W3, const float* __restrict__ b3,
                             const float* __restrict__ cbk)
{
    const int t = threadIdx.x;     // 1024 threads
    if (t == 0) g_stage.pad = 0.f;
    if (t < 96)  g_stage.W1d[t] = W1[12*32 + t];          // rows 12..14
    {
        const int c = t >> 5, j = t & 31;
        float a = b1[j];
        #pragma unroll
        for (int k = 0; k < FEAT; k++) a += cbk[c*FEAT + k] * W1[k*32 + j];
        g_stage.L1P[t] = a;
    }
    g_stage.W2[t] = W2[t];         // exactly 1024
    if (t < 32)  g_stage.B2[t] = b2[t];
    if (t < 96)  { const int c = t / 32, k = t % 32; g_stage.W3T[t] = W3[k*3 + c]; }
    if (t < 3)   g_stage.B3[t] = b3[t];
    if (t < NCB*FEAT) g_stage.CB[t] = cbk[t];
    if (t < NCB) {
        float a = 0.f;
        #pragma unroll
        for (int k = 0; k < FEAT; k++) { float v = cbk[t*FEAT + k]; a += v*v; }
        g_stage.C2[t] = a;
    }
}

__device__ __forceinline__ void load12(const float* __restrict__ p, float* dst) {
    float4 a = *(const float4*)(p);
    float4 b = *(const float4*)(p + 4);
    float4 c = *(const float4*)(p + 8);
    dst[0]=a.x; dst[1]=a.y; dst[2]=a.z;  dst[3]=a.w;
    dst[4]=b.x; dst[5]=b.y; dst[6]=b.z;  dst[7]=b.w;
    dst[8]=c.x; dst[9]=c.y; dst[10]=c.z; dst[11]=c.w;
}

__global__ __launch_bounds__(NT, 4)
void sky_kernel(const float* __restrict__ rays,
                const int* __restrict__ mask,
                const float* __restrict__ cube,
                float* __restrict__ out)
{
    __shared__ float sL1P[32*33];            // stride-33: conflict-free divergent row gather
    __shared__ float sRay[PIX_PER_BLOCK*3];  // block's rays, staged coalesced
    __shared__ int   sIdx[PIX_PER_BLOCK];
    __shared__ int   sCnt;

    const int tid  = threadIdx.x;
    const int lane = tid & 31;
    for (int j = tid; j < 32*32; j += NT) sL1P[(j >> 5)*33 + (j & 31)] = cC.L1P[j];
    if (tid == 0) sCnt = 0;

    // stage rays for this block's 512-pixel window (coalesced float4 loads)
    const int base = blockIdx.x * PIX_PER_BLOCK;
    {
        const float4* __restrict__ rsrc = (const float4*)(rays + (size_t)3 * base);
        float4* __restrict__ rdst = (float4*)sRay;
        #pragma unroll
        for (int j = 0; j < (PIX_PER_BLOCK*3/4 + NT - 1) / NT; j++) {
            const int idx = j * NT + tid;
            if (idx < PIX_PER_BLOCK*3/4) rdst[idx] = rsrc[idx];
        }
    }
    __syncthreads();

    // ---- phase 1: block-local compaction over 512 pixels + zero fills ----
    #pragma unroll
    for (int r = 0; r < PIX_PER_BLOCK / NT; r++) {
        const int pix = base + r * NT + tid;
        const bool active = (mask[pix] != 0);
        if (!active) {
            out[pix]          = 0.f;
            out[NPIX + pix]   = 0.f;
            out[2*NPIX + pix] = 0.f;
        }
        const unsigned bal = __ballot_sync(0xFFFFFFFFu, active);
        int wbase = 0;
        if (lane == 0) wbase = atomicAdd(&sCnt, __popc(bal));
        wbase = __shfl_sync(0xFFFFFFFFu, wbase, 0);
        if (active) sIdx[wbase + __popc(bal & ((1u << lane) - 1u))] = r * NT + tid;
    }
    __syncthreads();
    const int cnt = sCnt;

    // ---- phase 2: process compacted pixels with full warps ----
    for (int i = tid; i < cnt; i += NT) {
        const int li  = sIdx[i];
        const int pix = base + li;

        const float x = sRay[3*li+0], y = sRay[3*li+1], z = sRay[3*li+2];
        const float ax = fabsf(x), ay = fabsf(y), az = fabsf(z);
        const bool is_x = (ax >= ay) && (ax >= az);
        const bool is_y = (!is_x) && (ay >= az);

        int face; float ma, u, v;
        if (is_x)      { face = (x >= 0.f) ? 0 : 1; ma = ax; u = (x >= 0.f) ? -z : z; v = -y; }
        else if (is_y) { face = (y >= 0.f) ? 2 : 3; ma = ay; u = x; v = (y >= 0.f) ? z : -z; }
        else           { face = (z >= 0.f) ? 4 : 5; ma = az; u = (z >= 0.f) ? x : -x; v = -y; }

        const float inv = __fdividef(1.f, ma + 1e-9f);
        const float sc = (u*inv + 1.f) * 0.5f * (float)RES - 0.5f;
        const float tc = (v*inv + 1.f) * 0.5f * (float)RES - 0.5f;
        const float fs = floorf(sc), ft = floorf(tc);
        const float fx = sc - fs, fy = tc - ft;
        int x0 = (int)fs; x0 = max(0, min(x0, RES-1));
        const int x1 = min(x0+1, RES-1);
        int y0 = (int)ft; y0 = max(0, min(y0, RES-1));
        const int y1 = min(y0+1, RES-1);

        const float* __restrict__ fb = cube + (size_t)face * (size_t)(RES*RES*FEAT);

        float feat[FEAT], tmp[FEAT], bot[FEAT];
        load12(fb + ((size_t)y0*RES + x0)*FEAT, feat);
        load12(fb + ((size_t)y0*RES + x1)*FEAT, tmp);
        #pragma unroll
        for (int k = 0; k < FEAT; k++) feat[k] = feat[k]*(1.f-fx) + tmp[k]*fx;
        load12(fb + ((size_t)y1*RES + x0)*FEAT, bot);
        load12(fb + ((size_t)y1*RES + x1)*FEAT, tmp);
        #pragma unroll
        for (int k = 0; k < FEAT; k++) bot[k] = bot[k]*(1.f-fx) + tmp[k]*fx;
        #pragma unroll
        for (int k = 0; k < FEAT; k++) feat[k] = feat[k]*(1.f-fy) + bot[k]*fy;

        // nearest codebook: argmin_c (C2[c] - 2*dot), first-min-wins
        int best = 0;
        float bestd = 3.4e38f;
        #pragma unroll 4
        for (int c = 0; c < NCB; c++) {
            float dot = 0.f;
            #pragma unroll
            for (int k = 0; k < FEAT; k++) dot += feat[k]*cC.CB[c*FEAT + k];
            const float d2 = cC.C2[c] - 2.f*dot;
            if (d2 < bestd) { bestd = d2; best = c; }
        }

        // layer 1 (collapsed): relu(L1P[best] + x*W1[12] + y*W1[13] + z*W1[14])
        const float* __restrict__ rowp = sL1P + best*33;
        float h[32];
        #pragma unroll
        for (int j = 0; j < 32; j++) {
            float a = rowp[j];
            a += x * cC.W1d[j];
            a += y * cC.W1d[32 + j];
            a += z * cC.W1d[64 + j];
            h[j] = fmaxf(a, 0.f);
        }

        // layer 2: 32 -> 32, relu (weights in constant — LDC, small smem keeps L1D big)
        float h2[32];
        #pragma unroll
        for (int j = 0; j < 32; j++) h2[j] = cC.B2[j];
        #pragma unroll
        for (int k = 0; k < 32; k++) {
            const float iv = h[k];
            #pragma unroll
            for (int j = 0; j < 32; j++) h2[j] += iv * cC.W2[k*32 + j];
        }
        #pragma unroll
        for (int j = 0; j < 32; j++) h2[j] = fmaxf(h2[j], 0.f);

        // layer 3: 32 -> 3 with transposed weights (consecutive-k LDC.128), sigmoid
        float r0 = cC.B3[0], r1 = cC.B3[1], r2 = cC.B3[2];
        #pragma unroll
        for (int k = 0; k < 32; k++) {
            const float iv = h2[k];
            r0 += iv * cC.W3T[k];
            r1 += iv * cC.W3T[32 + k];
            r2 += iv * cC.W3T[64 + k];
        }
        // sigmoid already in (0,1): ref's clip is a no-op for active pixels
        out[pix]          = __fdividef(1.f, 1.f + __expf(-r0));
        out[NPIX + pix]   = __fdividef(1.f, 1.f + __expf(-r1));
        out[2*NPIX + pix] = __fdividef(1.f, 1.f + __expf(-r2));
    }
}

extern "C" void kernel_launch(void* const* d_in, const int* in_sizes, int n_in,
                              void* d_out, int out_size)
{
    const float* rays = (const float*)d_in[0];
    const int*   mask = (const int*)d_in[1];
    const float* cube = (const float*)d_in[2];
    const float* cbk  = (const float*)d_in[3];
    const float* W1   = (const float*)d_in[4];
    const float* b1   = (const float*)d_in[5];
    const float* W2   = (const float*)d_in[6];
    const float* b2   = (const float*)d_in[7];
    const float* W3   = (const float*)d_in[8];
    const float* b3   = (const float*)d_in[9];
    float* out = (float*)d_out;

    setup_kernel<<<1, 1024>>>(W1, b1, W2, b2, W3, b3, cbk);

    void* stage_ptr = nullptr;
    cudaGetSymbolAddress(&stage_ptr, g_stage);
    cudaMemcpyToSymbolAsync(cC, stage_ptr, sizeof(Consts), 0, cudaMemcpyDeviceToDevice, 0);

    sky_kernel<<<NPIX / PIX_PER_BLOCK, NT>>>(rays, mask, cube, out);
}